// round 6
// baseline (speedup 1.0000x reference)
#include <cuda_runtime.h>

// CorrelationMSELoss — B=8192 rows, L=1024 labels, single fused kernel.
// out = mean((pred-label)^2) + sum_rows(row_loss)

static constexpr int B_ROWS = 8192;
static constexpr int L_COLS = 1024;
static constexpr int WARPS_PER_BLOCK = 4;
static constexpr int THREADS = WARPS_PER_BLOCK * 32;       // 128
static constexpr int GRID = B_ROWS / WARPS_PER_BLOCK;      // 2048 blocks, one wave

__device__ float g_part_mse[GRID];
__device__ float g_part_loss[GRID];
__device__ unsigned int g_count = 0;  // reset by last block each launch

__device__ __forceinline__ float ex2_approx(float x) {
    float r;
    asm("ex2.approx.ftz.f32 %0, %1;" : "=f"(r) : "f"(x));
    return r;
}

__device__ __forceinline__ void accum_chunk(float4 p, float4 l, float& mse,
                                            float& spos, float& stot, float& none) {
    constexpr float L2E = 1.4426950408889634f;  // log2(e)
    float pe[4] = {p.x, p.y, p.z, p.w};
    float le[4] = {l.x, l.y, l.z, l.w};
#pragma unroll
    for (int j = 0; j < 4; ++j) {
        float pv = pe[j], lv = le[j];
        float d = pv - lv;
        mse = fmaf(d, d, mse);
        float t = pv * L2E;
        float arg = fmaf(lv, -2.f * t, t);  // +t for lv=0, -t for lv=1
        float e = ex2_approx(arg);
        stot += e;
        spos = fmaf(lv, e, spos);
        none += lv;  // exact integer count
    }
}

__global__ __launch_bounds__(THREADS, 16) void k_fused(const float* __restrict__ pred,
                                                       const float* __restrict__ label,
                                                       float* __restrict__ out) {
    const int lane = threadIdx.x & 31;
    const int warp = threadIdx.x >> 5;
    const int row = blockIdx.x * WARPS_PER_BLOCK + warp;

    const float4* p4 = reinterpret_cast<const float4*>(pred) + (long)row * (L_COLS / 4) + lane;
    const float4* l4 = reinterpret_cast<const float4*>(label) + (long)row * (L_COLS / 4) + lane;

    float mse = 0.f, spos = 0.f, stot = 0.f, none = 0.f;

#pragma unroll
    for (int i = 0; i < L_COLS / 4 / 32; ++i) {  // 8 iterations
        float4 p = __ldg(p4 + i * 32);
        float4 l = __ldg(l4 + i * 32);
        accum_chunk(p, l, mse, spos, stot, none);
    }

    // warp reduction (warp owns one row)
#pragma unroll
    for (int off = 16; off; off >>= 1) {
        mse  += __shfl_xor_sync(0xffffffffu, mse, off);
        spos += __shfl_xor_sync(0xffffffffu, spos, off);
        stot += __shfl_xor_sync(0xffffffffu, stot, off);
        none += __shfl_xor_sync(0xffffffffu, none, off);
    }

    __shared__ float s_mse[WARPS_PER_BLOCK];
    __shared__ float s_loss[WARPS_PER_BLOCK];
    __shared__ bool s_last;

    if (lane == 0) {
        float n1 = none;
        float n0 = (float)L_COLS - none;
        float sneg = stot - spos;
        float loss;
        if (n1 == 0.f) {
            loss = sneg * 0.36787944117144233f / fmaxf(n0, 1.f);  // e^{-1}*s_neg/n0
        } else if (n0 == 0.f) {
            loss = spos / n1;
        } else {
            loss = (spos * sneg) / (n1 * n0);
        }
        s_mse[warp] = mse;
        s_loss[warp] = loss;
    }
    __syncthreads();

    if (warp == 0 && lane < WARPS_PER_BLOCK) {
        float bm = s_mse[lane];
        float bl = s_loss[lane];
#pragma unroll
        for (int off = WARPS_PER_BLOCK / 2; off; off >>= 1) {
            bm += __shfl_xor_sync(0x0000000fu, bm, off);
            bl += __shfl_xor_sync(0x0000000fu, bl, off);
        }
        if (lane == 0) {
            g_part_mse[blockIdx.x] = bm;
            g_part_loss[blockIdx.x] = bl;
        }
    }

    // last-block final reduction (threadfence-reduction pattern)
    if (threadIdx.x == 0) {
        __threadfence();
        unsigned int prev = atomicAdd(&g_count, 1u);
        s_last = (prev == (unsigned)gridDim.x - 1u);
    }
    __syncthreads();

    if (s_last) {
        // GRID partials per array; THREADS threads, float4 strided
        const float4* pm4 = reinterpret_cast<const float4*>(g_part_mse);
        const float4* pl4 = reinterpret_cast<const float4*>(g_part_loss);
        double dm = 0.0, dl = 0.0;
#pragma unroll
        for (int i = 0; i < GRID / 4 / THREADS; ++i) {
            float4 vm = pm4[i * THREADS + threadIdx.x];
            float4 vl = pl4[i * THREADS + threadIdx.x];
            dm += (double)vm.x + (double)vm.y + (double)vm.z + (double)vm.w;
            dl += (double)vl.x + (double)vl.y + (double)vl.z + (double)vl.w;
        }
#pragma unroll
        for (int off = 16; off; off >>= 1) {
            dm += __shfl_xor_sync(0xffffffffu, dm, off);
            dl += __shfl_xor_sync(0xffffffffu, dl, off);
        }
        __shared__ double sd_m[WARPS_PER_BLOCK];
        __shared__ double sd_l[WARPS_PER_BLOCK];
        if (lane == 0) {
            sd_m[warp] = dm;
            sd_l[warp] = dl;
        }
        __syncthreads();
        if (threadIdx.x == 0) {
            double tm = 0.0, tl = 0.0;
#pragma unroll
            for (int w = 0; w < WARPS_PER_BLOCK; ++w) {
                tm += sd_m[w];
                tl += sd_l[w];
            }
            out[0] = (float)(tm * (1.0 / ((double)B_ROWS * (double)L_COLS)) + tl);
            g_count = 0;  // reset for next graph replay
        }
    }
}

extern "C" void kernel_launch(void* const* d_in, const int* in_sizes, int n_in,
                              void* d_out, int out_size) {
    const float* pred  = (const float*)d_in[0];
    const float* label = (const float*)d_in[1];
    float* out = (float*)d_out;
    k_fused<<<GRID, THREADS>>>(pred, label, out);
}

// round 7
// speedup vs baseline: 1.1544x; 1.1544x over previous
#include <cuda_runtime.h>

// CorrelationMSELoss — B=8192 rows, L=1024 labels, single fused kernel.
// out = mean((pred-label)^2) + sum_rows(row_loss)

static constexpr int B_ROWS = 8192;
static constexpr int L_COLS = 1024;
static constexpr int WARPS_PER_BLOCK = 8;
static constexpr int THREADS = WARPS_PER_BLOCK * 32;   // 256
static constexpr int GRID = B_ROWS / WARPS_PER_BLOCK;  // 1024 blocks

__device__ float g_part_mse[GRID];
__device__ float g_part_loss[GRID];
__device__ unsigned int g_count = 0;  // reset by last block each launch

__device__ __forceinline__ float ex2_approx(float x) {
    float r;
    asm("ex2.approx.ftz.f32 %0, %1;" : "=f"(r) : "f"(x));
    return r;
}

__device__ __forceinline__ void accum_chunk(float4 p, float4 l, float& mse,
                                            float& spos, float& stot, float& none) {
    constexpr float L2E = 1.4426950408889634f;  // log2(e)
    float pe[4] = {p.x, p.y, p.z, p.w};
    float le[4] = {l.x, l.y, l.z, l.w};
#pragma unroll
    for (int j = 0; j < 4; ++j) {
        float pv = pe[j], lv = le[j];
        float d = pv - lv;
        mse = fmaf(d, d, mse);
        float t = pv * L2E;
        float arg = fmaf(lv, -2.f * t, t);  // +t for lv=0, -t for lv=1
        float e = ex2_approx(arg);
        stot += e;
        spos = fmaf(lv, e, spos);
        none += lv;  // exact integer count
    }
}

__global__ __launch_bounds__(THREADS) void k_fused(const float* __restrict__ pred,
                                                   const float* __restrict__ label,
                                                   float* __restrict__ out) {
    const int lane = threadIdx.x & 31;
    const int warp = threadIdx.x >> 5;
    const int row = blockIdx.x * WARPS_PER_BLOCK + warp;

    const float4* p4 = reinterpret_cast<const float4*>(pred) + (long)row * (L_COLS / 4) + lane;
    const float4* l4 = reinterpret_cast<const float4*>(label) + (long)row * (L_COLS / 4) + lane;

    float mse = 0.f, spos = 0.f, stot = 0.f, none = 0.f;

    // 2 stages; each stage front-batches 8 independent LDG.128 (MLP_p1 = 8)
#pragma unroll
    for (int s = 0; s < 2; ++s) {
        float4 pr[4], lr[4];
#pragma unroll
        for (int i = 0; i < 4; ++i) pr[i] = __ldg(p4 + (s * 4 + i) * 32);
#pragma unroll
        for (int i = 0; i < 4; ++i) lr[i] = __ldg(l4 + (s * 4 + i) * 32);
#pragma unroll
        for (int i = 0; i < 4; ++i) accum_chunk(pr[i], lr[i], mse, spos, stot, none);
    }

    // warp reduction (warp owns one row)
#pragma unroll
    for (int off = 16; off; off >>= 1) {
        mse  += __shfl_xor_sync(0xffffffffu, mse, off);
        spos += __shfl_xor_sync(0xffffffffu, spos, off);
        stot += __shfl_xor_sync(0xffffffffu, stot, off);
        none += __shfl_xor_sync(0xffffffffu, none, off);
    }

    __shared__ float s_mse[WARPS_PER_BLOCK];
    __shared__ float s_loss[WARPS_PER_BLOCK];
    __shared__ bool s_last;

    if (lane == 0) {
        float n1 = none;
        float n0 = (float)L_COLS - none;
        float sneg = stot - spos;
        float loss;
        if (n1 == 0.f) {
            loss = sneg * 0.36787944117144233f / fmaxf(n0, 1.f);  // e^{-1}*s_neg/n0
        } else if (n0 == 0.f) {
            loss = spos / n1;
        } else {
            loss = (spos * sneg) / (n1 * n0);
        }
        s_mse[warp] = mse;
        s_loss[warp] = loss;
    }
    __syncthreads();

    if (warp == 0 && lane < WARPS_PER_BLOCK) {
        float bm = s_mse[lane];
        float bl = s_loss[lane];
#pragma unroll
        for (int off = 4; off; off >>= 1) {
            bm += __shfl_xor_sync(0x000000ffu, bm, off);
            bl += __shfl_xor_sync(0x000000ffu, bl, off);
        }
        if (lane == 0) {
            g_part_mse[blockIdx.x] = bm;
            g_part_loss[blockIdx.x] = bl;
        }
    }

    // last-block final reduction (threadfence-reduction pattern)
    if (threadIdx.x == 0) {
        __threadfence();
        unsigned int prev = atomicAdd(&g_count, 1u);
        s_last = (prev == (unsigned)gridDim.x - 1u);
    }
    __syncthreads();

    if (s_last) {
        // 1024 partials per array; 256 threads -> one float4 each
        const float4* pm4 = reinterpret_cast<const float4*>(g_part_mse);
        const float4* pl4 = reinterpret_cast<const float4*>(g_part_loss);
        float4 vm = pm4[threadIdx.x];
        float4 vl = pl4[threadIdx.x];
        double dm = (double)vm.x + (double)vm.y + (double)vm.z + (double)vm.w;
        double dl = (double)vl.x + (double)vl.y + (double)vl.z + (double)vl.w;
#pragma unroll
        for (int off = 16; off; off >>= 1) {
            dm += __shfl_xor_sync(0xffffffffu, dm, off);
            dl += __shfl_xor_sync(0xffffffffu, dl, off);
        }
        __shared__ double sd_m[WARPS_PER_BLOCK];
        __shared__ double sd_l[WARPS_PER_BLOCK];
        if (lane == 0) {
            sd_m[warp] = dm;
            sd_l[warp] = dl;
        }
        __syncthreads();
        if (threadIdx.x == 0) {
            double tm = 0.0, tl = 0.0;
#pragma unroll
            for (int w = 0; w < WARPS_PER_BLOCK; ++w) {
                tm += sd_m[w];
                tl += sd_l[w];
            }
            out[0] = (float)(tm * (1.0 / ((double)B_ROWS * (double)L_COLS)) + tl);
            g_count = 0;  // reset for next graph replay
        }
    }
}

extern "C" void kernel_launch(void* const* d_in, const int* in_sizes, int n_in,
                              void* d_out, int out_size) {
    const float* pred  = (const float*)d_in[0];
    const float* label = (const float*)d_in[1];
    float* out = (float*)d_out;
    k_fused<<<GRID, THREADS>>>(pred, label, out);
}